// round 10
// baseline (speedup 1.0000x reference)
#include <cuda_runtime.h>
#include <cuda_bf16.h>
#include <cstdint>
#include <cstddef>

#define DIM       128
#define ROWS_CTA  64
#define THREADS   256
#define KSEL      32
#define APITCH    136                       // bf16 elems per row (272 B, 16B-aligned)
#define AIMG      (ROWS_CTA*APITCH*2)       // 17408 B per x split image
#define BIMG      (128*APITCH*2)            // 34816 B per v split image
#define A_OFF     0
#define B_OFF     (2*AIMG)                  // 34816
#define STAGE_OFF B_OFF                     // overlays dead B region post-MMA
#define CAND_OFF  (B_OFF + 8*4*KSEL*8)      // +8192
#define SMEM_TOTAL (B_OFF + 2*BIMG)         // 104448 (2 CTAs/SM)
#define YPITCH    132                       // fp32 y pitch; y overlays A region
#define TAU       1.2e-3f                   // ambiguity threshold (~17 sigma of 2-split err)

__device__ float g_inv_len;
__device__ __align__(16) unsigned char g_vimg[2][BIMG];

// ---------------------------------------------------------------------------
__device__ __forceinline__ uint32_t smem_u32(const void* p) {
    uint32_t a;
    asm("{ .reg .u64 t; cvta.to.shared.u64 t, %1; cvt.u32.u64 %0, t; }"
        : "=r"(a) : "l"(p));
    return a;
}
__device__ __forceinline__ uint32_t pack_bf2(float lo, float hi) {
    uint32_t r;
    asm("cvt.rn.bf16x2.f32 %0, %1, %2;" : "=r"(r) : "f"(hi), "f"(lo));
    return r;
}
__device__ __forceinline__ unsigned fkey(float f) {
    unsigned u = __float_as_uint(f);
    return (u & 0x80000000u) ? ~u : (u | 0x80000000u);
}
__device__ __forceinline__ float unfkey(unsigned m) {
    unsigned u = (m & 0x80000000u) ? (m & 0x7fffffffu) : ~m;
    return __uint_as_float(u);
}
#define CSWAP(ka, ca, kb, cb)                                   \
    {                                                           \
        bool sw = (ka < kb) || (ka == kb && ca > cb);           \
        unsigned tk_ = sw ? kb : ka;                            \
        unsigned tc_ = sw ? cb : ca;                            \
        kb = sw ? ka : kb;  cb = sw ? ca : cb;                  \
        ka = tk_;           ca = tc_;                           \
    }

__device__ __forceinline__ void ldm_x4(uint32_t addr, uint32_t* r) {
    asm volatile("ldmatrix.sync.aligned.m8n8.x4.shared.b16 {%0,%1,%2,%3}, [%4];"
                 : "=r"(r[0]), "=r"(r[1]), "=r"(r[2]), "=r"(r[3]) : "r"(addr));
}
__device__ __forceinline__ void mma_bf16(float* c, const uint32_t* a,
                                         uint32_t b0, uint32_t b1) {
    asm volatile(
        "mma.sync.aligned.m16n8k16.row.col.f32.bf16.bf16.f32 "
        "{%0,%1,%2,%3}, {%4,%5,%6,%7}, {%8,%9}, {%0,%1,%2,%3};"
        : "+f"(c[0]), "+f"(c[1]), "+f"(c[2]), "+f"(c[3])
        : "r"(a[0]), "r"(a[1]), "r"(a[2]), "r"(a[3]), "r"(b0), "r"(b1));
}

// ---------------------------------------------------------------------------
// prep: 1/||v|| and bf16 2-split images of B[n][k] = v[k][n]
// ---------------------------------------------------------------------------
__global__ void prep_kernel(const float* __restrict__ v) {
    __shared__ float red[8];
    const int tid = threadIdx.x;
    float s = 0.f;
    for (int i = tid; i < DIM * DIM; i += 256) { float a = v[i]; s = fmaf(a, a, s); }
    #pragma unroll
    for (int o = 16; o; o >>= 1) s += __shfl_xor_sync(0xffffffffu, s, o);
    if ((tid & 31) == 0) red[tid >> 5] = s;
    __syncthreads();
    if (tid == 0) {
        float t = 0.f;
        #pragma unroll
        for (int i = 0; i < 8; i++) t += red[i];
        g_inv_len = 1.0f / sqrtf(t);
    }
    for (int i = tid; i < DIM * DIM; i += 256) {
        int k = i >> 7, n = i & 127;
        float a  = v[i];
        __nv_bfloat16 b0 = __float2bfloat16(a);
        float r1 = a - __bfloat162float(b0);
        uint32_t off = (uint32_t)(n * APITCH + k) * 2;
        *(__nv_bfloat16*)(g_vimg[0] + off) = b0;
        *(__nv_bfloat16*)(g_vimg[1] + off) = __float2bfloat16(r1);
    }
}

// ---------------------------------------------------------------------------
// rare-path fixup: exact (ascending-k fp32 fma) re-rank of ambiguous rows
// ---------------------------------------------------------------------------
__device__ __noinline__ void fixup_row(const float* __restrict__ x,
                                       const float* __restrict__ vfp,
                                       int grow, const float* __restrict__ ysh_row,
                                       uint2* st_row, int* candbuf, float y31) {
    const int lane = threadIdx.x & 31;
    const int col0 = (31 - lane) * 4;
    const float yt = y31 - TAU;

    int base = 0;
    #pragma unroll
    for (int q = 0; q < 4; ++q) {
        int c = col0 + q;
        bool sel = (ysh_row[c] >= yt);
        unsigned bal = __ballot_sync(0xffffffffu, sel);
        int pos = base + __popc(bal & ((1u << lane) - 1u));
        if (sel && pos < 64) candbuf[pos] = c;
        base += __popc(bal);
    }
    int ncand = base < 64 ? base : 64;
    __syncwarp();

    int c1 = (lane < ncand) ? candbuf[lane] : -1;
    int c2 = (lane + 32 < ncand) ? candbuf[lane + 32] : -1;
    const float* xr = x + (size_t)grow * DIM;
    const float* v1 = vfp + ((c1 >= 0) ? c1 : 0);
    const float* v2 = vfp + ((c2 >= 0) ? c2 : 0);
    float a1 = 0.f, a2 = 0.f;
    #pragma unroll 4
    for (int k = 0; k < DIM; ++k) {
        float xv = __ldg(xr + k);
        a1 = fmaf(xv, __ldg(v1 + (size_t)k * DIM), a1);
        a2 = fmaf(xv, __ldg(v2 + (size_t)k * DIM), a2);
    }

    unsigned hk = (c1 >= 0) ? fkey(a1) : 0u;
    unsigned hc = (c1 >= 0) ? (unsigned)c1 : 0x7fffffffu;
    unsigned tk = (c2 >= 0) ? fkey(a2) : 0u;
    unsigned tc = (c2 >= 0) ? (unsigned)c2 : 0x7fffffffu;
    CSWAP(hk, hc, tk, tc);

    #pragma unroll 1
    for (int i = 0; i < KSEL; ++i) {
        unsigned m = __reduce_max_sync(0xffffffffu, hk);
        bool sel = (hk == m);
        unsigned colx = sel ? hc : 0x7fffffffu;
        unsigned minc = __reduce_min_sync(0xffffffffu, colx);   // jax tie-break
        bool win = sel && (hc == minc);
        if (win) st_row[i] = make_uint2(hc, hk);
        hk = win ? tk : hk;  hc = win ? tc : hc;  tk = win ? 0u : tk;
    }
    __syncwarp();
}

// ---------------------------------------------------------------------------
// main fused kernel: 2-split -> HMMA (3 products) -> y SMEM -> top-32 -> out
// ---------------------------------------------------------------------------
__global__ __launch_bounds__(THREADS, 2)
void pool_kernel(const float* __restrict__ x, const float* __restrict__ vfp,
                 float* __restrict__ out, int nrows) {
    extern __shared__ __align__(16) char smem_c[];
    const uint32_t smem_base = smem_u32(smem_c);
    const int tid  = threadIdx.x;
    const int warp = tid >> 5, lane = tid & 31;
    const int row0 = blockIdx.x * ROWS_CTA;

    // ---- copy v split images ----
    {
        const float4* vg = (const float4*)g_vimg;
        float4* vs = (float4*)(smem_c + B_OFF);
        for (int i = tid; i < 2 * BIMG / 16; i += THREADS) vs[i] = vg[i];
    }

    // ---- load x tile, 2-way rn-bf16 split ----
    for (int i = tid; i < ROWS_CTA * DIM / 4; i += THREADS) {
        int row = i >> 5;
        int k4  = (i & 31) << 2;
        int grow = row0 + row;
        float4 a = make_float4(0.f, 0.f, 0.f, 0.f);
        if (grow < nrows) a = *(const float4*)(x + (size_t)grow * DIM + k4);

        uint32_t p0xy = pack_bf2(a.x, a.y);
        uint32_t p0zw = pack_bf2(a.z, a.w);
        float x0 = __uint_as_float(p0xy << 16), y0 = __uint_as_float(p0xy & 0xFFFF0000u);
        float z0 = __uint_as_float(p0zw << 16), w0 = __uint_as_float(p0zw & 0xFFFF0000u);
        uint32_t p1xy = pack_bf2(a.x - x0, a.y - y0);
        uint32_t p1zw = pack_bf2(a.z - z0, a.w - w0);

        uint32_t off = (uint32_t)(row * APITCH + k4) * 2;
        *(uint2*)(smem_c + A_OFF + 0 * AIMG + off) = make_uint2(p0xy, p0zw);
        *(uint2*)(smem_c + A_OFF + 1 * AIMG + off) = make_uint2(p1xy, p1zw);
    }
    __syncthreads();

    // ---- HMMA: warp -> 16 rows x 64 cols; 3 split products ----
    const int mw = warp & 3, nh = warp >> 2;
    const int wr0 = mw * 16;
    const int n_base = nh * 64;
    const int g = lane >> 3, lr = lane & 7;
    const uint32_t a_addr = smem_base + A_OFF +
        (uint32_t)((wr0 + lr + (g & 1) * 8) * APITCH + (g >> 1) * 8) * 2;
    const uint32_t b_addr = smem_base + B_OFF +
        (uint32_t)((n_base + lr + (g >> 1) * 8) * APITCH + (g & 1) * 8) * 2;

    float C[8][4];
    #pragma unroll
    for (int i = 0; i < 8; i++)
        #pragma unroll
        for (int j = 0; j < 4; j++) C[i][j] = 0.f;

    #pragma unroll
    for (int k = 0; k < 8; ++k) {
        uint32_t A[2][4];
        #pragma unroll
        for (int im = 0; im < 2; ++im)
            ldm_x4(a_addr + im * AIMG + k * 32, A[im]);
        #pragma unroll
        for (int ntp = 0; ntp < 4; ++ntp) {
            uint32_t B[2][4];
            #pragma unroll
            for (int im = 0; im < 2; ++im)
                ldm_x4(b_addr + im * BIMG + ntp * (16 * APITCH * 2) + k * 32, B[im]);
            float* c0 = C[2 * ntp];
            float* c1 = C[2 * ntp + 1];
            mma_bf16(c0, A[0], B[0][0], B[0][1]); mma_bf16(c1, A[0], B[0][2], B[0][3]);
            mma_bf16(c0, A[0], B[1][0], B[1][1]); mma_bf16(c1, A[0], B[1][2], B[1][3]);
            mma_bf16(c0, A[1], B[0][0], B[0][1]); mma_bf16(c1, A[1], B[0][2], B[0][3]);
        }
    }
    __syncthreads();     // A and B images dead; reuse A for y, B for stage/cand

    // ---- write y fragments to SMEM (y overlays A region) ----
    float* ysh = (float*)(smem_c + A_OFF);
    {
        const int r = lane >> 2, q = lane & 3;
        #pragma unroll
        for (int nt = 0; nt < 8; ++nt) {
            int col = n_base + nt * 8 + 2 * q;
            *(float2*)(ysh + (wr0 + r) * YPITCH + col)     = make_float2(C[nt][0], C[nt][1]);
            *(float2*)(ysh + (wr0 + 8 + r) * YPITCH + col) = make_float2(C[nt][2], C[nt][3]);
        }
    }
    __syncthreads();

    // ---- selection: warp -> 8 rows, 4-row interleave, jax tie-break ----
    const float inv_len = g_inv_len;
    const int r0 = warp * 8;
    const int col0 = (31 - lane) * 4;           // FLO(ballot) -> lowest column
    uint2* st = (uint2*)(smem_c + STAGE_OFF) + warp * 4 * KSEL;
    int* candw = (int*)(smem_c + CAND_OFF) + warp * 64;

    #pragma unroll 1
    for (int pass = 0; pass < 2; ++pass) {
        unsigned kk[4][4], cc[4][4];
        #pragma unroll
        for (int j = 0; j < 4; ++j) {
            int row = r0 + pass * 4 + j;
            float4 y4 = *(const float4*)(ysh + row * YPITCH + col0);
            kk[j][0] = fkey(y4.x); kk[j][1] = fkey(y4.y);
            kk[j][2] = fkey(y4.z); kk[j][3] = fkey(y4.w);
            cc[j][0] = col0 + 0; cc[j][1] = col0 + 1;
            cc[j][2] = col0 + 2; cc[j][3] = col0 + 3;
            CSWAP(kk[j][0], cc[j][0], kk[j][1], cc[j][1]);
            CSWAP(kk[j][2], cc[j][2], kk[j][3], cc[j][3]);
            CSWAP(kk[j][0], cc[j][0], kk[j][2], cc[j][2]);
            CSWAP(kk[j][1], cc[j][1], kk[j][3], cc[j][3]);
            CSWAP(kk[j][1], cc[j][1], kk[j][2], cc[j][2]);
        }

        #pragma unroll 4
        for (int i = 0; i < KSEL; ++i) {
            #pragma unroll
            for (int j = 0; j < 4; ++j) {
                unsigned m   = __reduce_max_sync(0xffffffffu, kk[j][0]);
                unsigned bal = __ballot_sync(0xffffffffu, kk[j][0] == m);
                bool win = (lane == 31 - __clz(bal));
                if (win) st[j * KSEL + i] = make_uint2(cc[j][0], kk[j][0]);
                kk[j][0] = win ? kk[j][1] : kk[j][0];  cc[j][0] = win ? cc[j][1] : cc[j][0];
                kk[j][1] = win ? kk[j][2] : kk[j][1];  cc[j][1] = win ? cc[j][2] : cc[j][1];
                kk[j][2] = win ? kk[j][3] : kk[j][2];  cc[j][2] = win ? cc[j][3] : cc[j][2];
                kk[j][3] = win ? 0u       : kk[j][3];
            }
        }
        __syncwarp();

        // ---- gap check, rare exact fixup, output ----
        #pragma unroll
        for (int j = 0; j < 4; ++j) {
            const int rowl = r0 + pass * 4 + j;
            const int grow = row0 + rowl;
            if (grow < nrows) {
                uint2 p = st[j * KSEL + lane];
                float yl = unfkey(p.y);
                float y33 = unfkey(__reduce_max_sync(0xffffffffu, kk[j][0]));
                float ynext = __shfl_down_sync(0xffffffffu, yl, 1);
                if (lane == 31) ynext = y33;
                if (__ballot_sync(0xffffffffu, (yl - ynext) < TAU)) {
                    float y31 = __shfl_sync(0xffffffffu, yl, 31);
                    fixup_row(x, vfp, grow, ysh + rowl * YPITCH,
                              st + j * KSEL, candw, y31);
                    p = st[j * KSEL + lane];
                }
                float d  = unfkey(p.y) * inv_len;
                float sg = 1.0f / (1.0f + __expf(-d));
                float xv = __ldg(&x[(size_t)grow * DIM + p.x]);
                out[(size_t)grow * KSEL + lane] = xv * sg;
            }
            __syncwarp();
        }
    }
}

// ---------------------------------------------------------------------------
extern "C" void kernel_launch(void* const* d_in, const int* in_sizes, int n_in,
                              void* d_out, int out_size) {
    const float* x = (const float*)d_in[0];
    const float* v = (const float*)d_in[1];
    float* out = (float*)d_out;
    const int nrows = in_sizes[0] / DIM;

    cudaFuncSetAttribute(pool_kernel,
                         cudaFuncAttributeMaxDynamicSharedMemorySize, SMEM_TOTAL);

    prep_kernel<<<1, 256>>>(v);
    const int grid = (nrows + ROWS_CTA - 1) / ROWS_CTA;
    pool_kernel<<<grid, THREADS, SMEM_TOTAL>>>(x, v, out, nrows);
}

// round 11
// speedup vs baseline: 1.7430x; 1.7430x over previous
#include <cuda_runtime.h>
#include <cstdint>
#include <cstddef>

#define DIM      128
#define ROWS     64          // rows per block
#define THREADS  256
#define RPW      8           // rows per warp
#define XPITCH   68          // padded pitch (floats) of transposed x tile
#define KSEL     32
#define VCHUNK   32          // d-rows of v staged per pass (4 passes)

// smem: v chunk [32][128] + x^T [128][68] + stage [8 warps][2 rows][32] uint2
#define SMEM_BYTES (VCHUNK*DIM*4 + DIM*XPITCH*4 + 8*2*KSEL*8)

__device__ float g_inv_len;

// ---------------------------------------------------------------------------
// helpers
// ---------------------------------------------------------------------------
__device__ __forceinline__ unsigned long long dup_f32(float a) {
    unsigned long long r; unsigned u = __float_as_uint(a);
    asm("mov.b64 %0, {%1, %1};" : "=l"(r) : "r"(u));
    return r;
}
__device__ __forceinline__ void fma2(unsigned long long& c,
                                     unsigned long long a,
                                     unsigned long long b) {
    asm("fma.rn.f32x2 %0, %1, %2, %0;" : "+l"(c) : "l"(a), "l"(b));
}
// order-preserving float -> u32 key (larger float => larger key)
__device__ __forceinline__ unsigned fkey(float f) {
    unsigned u = __float_as_uint(f);
    return (u & 0x80000000u) ? ~u : (u | 0x80000000u);
}
__device__ __forceinline__ float unfkey(unsigned m) {
    unsigned u = (m & 0x80000000u) ? (m & 0x7fffffffu) : ~m;
    return __uint_as_float(u);
}

union F2U { unsigned long long u; float2 f; };

// stable desc comparator: larger key first; equal keys -> lower col first
#define CSWAP(ka, ca, kb, cb)                                   \
    {                                                           \
        bool sw = (ka < kb) || (ka == kb && ca > cb);           \
        unsigned tk = sw ? kb : ka;                             \
        unsigned tc = sw ? cb : ca;                             \
        kb = sw ? ka : kb;  cb = sw ? ca : cb;                  \
        ka = tk;            ca = tc;                            \
    }

// ---------------------------------------------------------------------------
// 1/||v||_F  (one block)
// ---------------------------------------------------------------------------
__global__ void norm_kernel(const float* __restrict__ v) {
    __shared__ float red[8];
    float s = 0.f;
    for (int i = threadIdx.x; i < DIM * DIM; i += blockDim.x) {
        float a = v[i];
        s = fmaf(a, a, s);
    }
    #pragma unroll
    for (int o = 16; o; o >>= 1) s += __shfl_xor_sync(0xffffffffu, s, o);
    if ((threadIdx.x & 31) == 0) red[threadIdx.x >> 5] = s;
    __syncthreads();
    if (threadIdx.x == 0) {
        float t = 0.f;
        #pragma unroll
        for (int i = 0; i < 8; i++) t += red[i];
        g_inv_len = 1.0f / sqrtf(t);
    }
}

// ---------------------------------------------------------------------------
// fused  y = x@v ; top-32 per row ; out = x[idx] * sigmoid(y[idx]/||v||)
// ---------------------------------------------------------------------------
__global__ __launch_bounds__(THREADS, 4)
void pool_kernel(const float* __restrict__ x, const float* __restrict__ v,
                 float* __restrict__ out, int nrows) {
    extern __shared__ float smem[];
    float* v_sh = smem;                           // [32][128], per pass
    float* x_sh = smem + VCHUNK * DIM;            // transposed: [d][row], pitch 68
    uint2* stage = (uint2*)(x_sh + DIM * XPITCH); // [8 warps][2][32]

    const int tid  = threadIdx.x;
    const int row0 = blockIdx.x * ROWS;
    const int warp = tid >> 5, lane = tid & 31;
    const int r0 = warp * RPW;

    // ---- load x tile transposed (one-off) ----
    for (int e = tid; e < ROWS * DIM; e += THREADS) {
        int r = e >> 7, d = e & 127;
        float val = (row0 + r < nrows) ? x[(size_t)(row0 + r) * DIM + d] : 0.f;
        x_sh[d * XPITCH + r] = val;
    }

    // lane l owns columns (31-l)*4 .. (31-l)*4+3  (so FLO(ballot) = lowest col)
    const int col0 = (31 - lane) * 4;

    unsigned long long acc[4][4];
    #pragma unroll
    for (int a = 0; a < 4; a++)
        #pragma unroll
        for (int b = 0; b < 4; b++) acc[a][b] = 0ull;

    // ---- GEMM in four d-passes (v staged 32 rows at a time) ----
    #pragma unroll 1
    for (int pass = 0; pass < 4; ++pass) {
        __syncthreads();   // pass0: pairs with x load; later: v_sh reuse fence
        {
            const float4* vg = (const float4*)(v + pass * VCHUNK * DIM);
            float4*       vs = (float4*)v_sh;
            for (int i = tid; i < VCHUNK * DIM / 4; i += THREADS) vs[i] = vg[i];
        }
        __syncthreads();

        const float* vcol  = v_sh + col0;
        const float* xbase = x_sh + pass * VCHUNK * XPITCH + r0;

        #pragma unroll 8
        for (int dd = 0; dd < VCHUNK; ++dd) {
            float4 vv = *(const float4*)(vcol + (size_t)dd * DIM);
            const float* xr = xbase + dd * XPITCH;
            ulonglong2 xa = *(const ulonglong2*)(xr + 0);   // x01 | x23
            ulonglong2 xb = *(const ulonglong2*)(xr + 4);   // x45 | x67
            unsigned long long v0 = dup_f32(vv.x), v1 = dup_f32(vv.y);
            unsigned long long v2 = dup_f32(vv.z), v3 = dup_f32(vv.w);
            fma2(acc[0][0], xa.x, v0); fma2(acc[0][1], xa.x, v1);
            fma2(acc[0][2], xa.x, v2); fma2(acc[0][3], xa.x, v3);
            fma2(acc[1][0], xa.y, v0); fma2(acc[1][1], xa.y, v1);
            fma2(acc[1][2], xa.y, v2); fma2(acc[1][3], xa.y, v3);
            fma2(acc[2][0], xb.x, v0); fma2(acc[2][1], xb.x, v1);
            fma2(acc[2][2], xb.x, v2); fma2(acc[2][3], xb.x, v3);
            fma2(acc[3][0], xb.y, v0); fma2(acc[3][1], xb.y, v1);
            fma2(acc[3][2], xb.y, v2); fma2(acc[3][3], xb.y, v3);
        }
    }

    const float inv_len = g_inv_len;
    uint2* stA = stage + warp * 2 * KSEL;
    uint2* stB = stA + KSEL;

    // ---- top-32 per row: branch-free, two rows interleaved per loop ----
    #pragma unroll
    for (int pr = 0; pr < 4; ++pr) {
        F2U t0, t1, t2, t3;
        t0.u = acc[pr][0]; t1.u = acc[pr][1];
        t2.u = acc[pr][2]; t3.u = acc[pr][3];

        // row A = local row r0+2*pr (low halves), row B = r0+2*pr+1 (high)
        unsigned kA0 = fkey(t0.f.x), kA1 = fkey(t1.f.x),
                 kA2 = fkey(t2.f.x), kA3 = fkey(t3.f.x);
        unsigned kB0 = fkey(t0.f.y), kB1 = fkey(t1.f.y),
                 kB2 = fkey(t2.f.y), kB3 = fkey(t3.f.y);
        unsigned cA0 = col0 + 0, cA1 = col0 + 1, cA2 = col0 + 2, cA3 = col0 + 3;
        unsigned cB0 = cA0, cB1 = cA1, cB2 = cA2, cB3 = cA3;

        // sort each lane's 4 candidates descending (stable on col)
        CSWAP(kA0, cA0, kA1, cA1); CSWAP(kA2, cA2, kA3, cA3);
        CSWAP(kA0, cA0, kA2, cA2); CSWAP(kA1, cA1, kA3, cA3);
        CSWAP(kA1, cA1, kA2, cA2);
        CSWAP(kB0, cB0, kB1, cB1); CSWAP(kB2, cB2, kB3, cB3);
        CSWAP(kB0, cB0, kB2, cB2); CSWAP(kB1, cB1, kB3, cB3);
        CSWAP(kB1, cB1, kB2, cB2);

        #pragma unroll 4
        for (int i = 0; i < KSEL; ++i) {
            unsigned mA = __reduce_max_sync(0xffffffffu, kA0);
            unsigned mB = __reduce_max_sync(0xffffffffu, kB0);
            unsigned balA = __ballot_sync(0xffffffffu, kA0 == mA);
            unsigned balB = __ballot_sync(0xffffffffu, kB0 == mB);
            bool winA = (lane == 31 - __clz(balA));   // FLO -> lowest column
            bool winB = (lane == 31 - __clz(balB));
            if (winA) stA[i] = make_uint2(cA0, kA0);
            if (winB) stB[i] = make_uint2(cB0, kB0);
            kA0 = winA ? kA1 : kA0;  cA0 = winA ? cA1 : cA0;
            kA1 = winA ? kA2 : kA1;  cA1 = winA ? cA2 : cA1;
            kA2 = winA ? kA3 : kA2;  cA2 = winA ? cA3 : cA2;
            kA3 = winA ? 0u  : kA3;
            kB0 = winB ? kB1 : kB0;  cB0 = winB ? cB1 : cB0;
            kB1 = winB ? kB2 : kB1;  cB1 = winB ? cB2 : cB1;
            kB2 = winB ? kB3 : kB2;  cB2 = winB ? cB3 : cB2;
            kB3 = winB ? 0u  : kB3;
        }
        __syncwarp();

        // ---- epilogue: gather x, sigmoid, store (lane i -> rank i) ----
        {
            const int rowA = r0 + 2 * pr;
            const int growA = row0 + rowA;
            uint2 pA = stA[lane];
            uint2 pB = stB[lane];
            float dA = unfkey(pA.y) * inv_len;
            float dB = unfkey(pB.y) * inv_len;
            float sA = 1.0f / (1.0f + __expf(-dA));
            float sB = 1.0f / (1.0f + __expf(-dB));
            float xA = x_sh[pA.x * XPITCH + rowA];
            float xB = x_sh[pB.x * XPITCH + rowA + 1];
            if (growA < nrows)
                out[(size_t)growA * KSEL + lane] = xA * sA;
            if (growA + 1 < nrows)
                out[(size_t)(growA + 1) * KSEL + lane] = xB * sB;
        }
        __syncwarp();
    }
}

// ---------------------------------------------------------------------------
extern "C" void kernel_launch(void* const* d_in, const int* in_sizes, int n_in,
                              void* d_out, int out_size) {
    const float* x = (const float*)d_in[0];
    const float* v = (const float*)d_in[1];
    float* out = (float*)d_out;
    const int nrows = in_sizes[0] / DIM;

    cudaFuncSetAttribute(pool_kernel,
                         cudaFuncAttributeMaxDynamicSharedMemorySize, SMEM_BYTES);

    norm_kernel<<<1, 256>>>(v);
    const int grid = (nrows + ROWS - 1) / ROWS;
    pool_kernel<<<grid, THREADS, SMEM_BYTES>>>(x, v, out, nrows);
}